// round 5
// baseline (speedup 1.0000x reference)
#include <cuda_runtime.h>
#include <cstdint>
#include <math.h>

#define T_TOKENS 8192
#define HIDDEN   5120
#define NQ       40
#define NKV      10
#define HD       128
#define QKV_N    7680
#define S_LEN    1024
#define KDIM     5120

// Scratch (device globals: no allocation allowed anywhere)
__device__ float g_qkv[(size_t)T_TOKENS * QKV_N];
__device__ float g_obuf[(size_t)T_TOKENS * HIDDEN];
__device__ float g_xr [(size_t)T_TOKENS * HIDDEN];   // tf32-rounded x
__device__ float g_wa [(size_t)HIDDEN * QKV_N];      // tf32-rounded w_qkv^T [7680][5120]
__device__ float g_wb [(size_t)HIDDEN * HIDDEN];     // tf32-rounded w_o^T   [5120][5120]

// ===========================================================================
// helpers
// ===========================================================================
__device__ __forceinline__ uint32_t smem_u32(const void* p) {
    uint32_t a;
    asm("{ .reg .u64 t; cvta.to.shared.u64 t, %1; cvt.u32.u64 %0, t; }"
        : "=r"(a) : "l"(p));
    return a;
}

__device__ __forceinline__ uint32_t tf32r(float x) {
    uint32_t u;
    asm("cvt.rna.tf32.f32 %0, %1;" : "=r"(u) : "f"(x));
    return u;
}

__device__ __forceinline__ void cp_async16(uint32_t dst, const void* src) {
    asm volatile("cp.async.cg.shared.global [%0], [%1], 16;"
                 :: "r"(dst), "l"(src) : "memory");
}

__device__ __forceinline__ void ldsm_x4(uint32_t* r, uint32_t addr) {
    asm volatile("ldmatrix.sync.aligned.m8n8.x4.shared.b16 {%0,%1,%2,%3}, [%4];"
                 : "=r"(r[0]), "=r"(r[1]), "=r"(r[2]), "=r"(r[3]) : "r"(addr));
}

__device__ __forceinline__ void mma_tf32(float* d, const uint32_t* a,
                                         uint32_t b0, uint32_t b1) {
    asm volatile(
        "mma.sync.aligned.m16n8k8.row.col.f32.tf32.tf32.f32 "
        "{%0,%1,%2,%3}, {%4,%5,%6,%7}, {%8,%9}, {%0,%1,%2,%3};"
        : "+f"(d[0]), "+f"(d[1]), "+f"(d[2]), "+f"(d[3])
        : "r"(a[0]), "r"(a[1]), "r"(a[2]), "r"(a[3]), "r"(b0), "r"(b1));
}

// ===========================================================================
// tf32 rounded copy (no transpose) — for x
// ===========================================================================
__global__ void cvt_tf32_kernel(const float4* __restrict__ src,
                                float4* __restrict__ dst, int n4)
{
    int i = blockIdx.x * blockDim.x + threadIdx.x;
    if (i >= n4) return;
    float4 v = src[i];
    float4 o;
    o.x = __uint_as_float(tf32r(v.x));
    o.y = __uint_as_float(tf32r(v.y));
    o.z = __uint_as_float(tf32r(v.z));
    o.w = __uint_as_float(tf32r(v.w));
    dst[i] = o;
}

// ===========================================================================
// tf32 rounded transpose: src [R][C] -> dst [C][R]. R,C % 32 == 0.
// ===========================================================================
__global__ void transpose_tf32_kernel(const float* __restrict__ src,
                                      float* __restrict__ dst, int R, int C)
{
    __shared__ float tile[32][33];
    int bc = blockIdx.x * 32, br = blockIdx.y * 32;
    int tx = threadIdx.x, ty = threadIdx.y;
#pragma unroll
    for (int i = 0; i < 32; i += 8) {
        float v = src[(size_t)(br + ty + i) * C + bc + tx];
        tile[ty + i][tx] = __uint_as_float(tf32r(v));
    }
    __syncthreads();
#pragma unroll
    for (int i = 0; i < 32; i += 8)
        dst[(size_t)(bc + ty + i) * R + br + tx] = tile[tx][ty + i];
}

// ===========================================================================
// TF32 mma.sync GEMM: C[M,N] = A[M,K] @ Bt[N,K]^T, all row-major storage.
// Block 128x256, BK=32, 8 warps (2 x 4), warp tile 64x64.
// Both A and Bt staged K-major in smem with 144-byte row pitch; all
// fragments via ldmatrix. 3-stage cp.async pipeline, 1 CTA/SM.
// ===========================================================================
#define A_ST_B 18432             // 128 rows * 144 B
#define B_ST_B 36864             // 256 rows * 144 B
#define STAGE_B (A_ST_B + B_ST_B)   // 55296
#define GEMM_SMEM (3 * STAGE_B)     // 165888

__global__ __launch_bounds__(256, 1)
void tc_gemm(const float* __restrict__ A, const float* __restrict__ Bt,
             float* __restrict__ C, int M, int N, int K)
{
    extern __shared__ __align__(16) char smem[];
    const uint32_t sbase = smem_u32(smem);
    const int tid  = threadIdx.x;
    const int lane = tid & 31;
    const int wid  = tid >> 5;
    const int wm   = wid & 1;        // 0..1  (64 rows each)
    const int wn   = wid >> 1;       // 0..3  (64 cols each)
    const int bm = blockIdx.y * 128, bn = blockIdx.x * 256;

    const float* Ag = A  + (size_t)bm * K;
    const float* Bg = Bt + (size_t)bn * K;

    float acc[4][8][4];
#pragma unroll
    for (int i = 0; i < 4; i++)
#pragma unroll
        for (int j = 0; j < 8; j++)
#pragma unroll
            for (int q = 0; q < 4; q++) acc[i][j][q] = 0.0f;

    // ---- async copy of chunk c into stage st ----
#define ISSUE_CHUNK(c, st) do {                                              \
        uint32_t a_dst = sbase + (st) * STAGE_B;                             \
        uint32_t b_dst = a_dst + A_ST_B;                                     \
        _Pragma("unroll")                                                    \
        for (int i = 0; i < 4; i++) {                                        \
            int idx = i * 256 + tid;                                         \
            int row = idx >> 3, kq = idx & 7;                                \
            cp_async16(a_dst + row * 144 + kq * 16,                          \
                       Ag + (size_t)row * K + (c) * 32 + kq * 4);            \
        }                                                                    \
        _Pragma("unroll")                                                    \
        for (int i = 0; i < 8; i++) {                                        \
            int idx = i * 256 + tid;                                         \
            int row = idx >> 3, kq = idx & 7;                                \
            cp_async16(b_dst + row * 144 + kq * 16,                          \
                       Bg + (size_t)row * K + (c) * 32 + kq * 4);            \
        }                                                                    \
        asm volatile("cp.async.commit_group;" ::: "memory");                 \
    } while (0)

    ISSUE_CHUNK(0, 0);
    ISSUE_CHUNK(1, 1);

    // per-thread ldmatrix bases
    // A: lanes 0-7 rows r0..r7 (k-quad 0), 8-15 rows r8..r15, 16-31 same +16B
    const uint32_t a_tbase = sbase
        + (uint32_t)((wm * 64 + ((lane >> 3) & 1) * 8 + (lane & 7)) * 144)
        + (uint32_t)((lane >> 4) * 16);
    // B: lanes 0-7 n-rows 0..7 quad0; 8-15 rows 0..7 quad1;
    //    16-23 rows 8..15 quad0; 24-31 rows 8..15 quad1
    const uint32_t b_tbase = sbase + A_ST_B
        + (uint32_t)((wn * 64 + (lane & 7) + ((lane >> 4) << 3)) * 144)
        + (uint32_t)(((lane >> 3) & 1) * 16);

    const int NCH = K / 32;
    for (int c = 0; c < NCH; c++) {
        const int st = c % 3;
        asm volatile("cp.async.wait_group 1;" ::: "memory");
        __syncthreads();
        if (c + 2 < NCH) ISSUE_CHUNK(c + 2, (c + 2) % 3);

        const uint32_t a_base = a_tbase + st * STAGE_B;
        const uint32_t b_base = b_tbase + st * STAGE_B;

#pragma unroll
        for (int j = 0; j < 4; j++) {
            uint32_t afr[4][4];
#pragma unroll
            for (int mt = 0; mt < 4; mt++)
                ldsm_x4(afr[mt], a_base + mt * 2304 + j * 32);   // 2304 = 16*144

            uint32_t bfr[4][4];
#pragma unroll
            for (int p = 0; p < 4; p++)
                ldsm_x4(bfr[p], b_base + p * 2304 + j * 32);

#pragma unroll
            for (int mt = 0; mt < 4; mt++)
#pragma unroll
                for (int nt = 0; nt < 8; nt++)
                    mma_tf32(acc[mt][nt], afr[mt],
                             bfr[nt >> 1][(nt & 1) * 2],
                             bfr[nt >> 1][(nt & 1) * 2 + 1]);
        }
    }

    // Epilogue
    const int erow = bm + wm * 64 + (lane >> 2);
    const int ecol = bn + wn * 64 + 2 * (lane & 3);
#pragma unroll
    for (int mt = 0; mt < 4; mt++) {
#pragma unroll
        for (int nt = 0; nt < 8; nt++) {
            float* p0 = C + (size_t)(erow + mt * 16) * N + ecol + nt * 8;
            float* p1 = p0 + 8 * N;
            *(float2*)p0 = make_float2(acc[mt][nt][0], acc[mt][nt][1]);
            *(float2*)p1 = make_float2(acc[mt][nt][2], acc[mt][nt][3]);
        }
    }
#undef ISSUE_CHUNK
}

// ===========================================================================
// RoPE in-place on q (heads 0..39) and k (heads 40..49) of g_qkv.
// ===========================================================================
__global__ void rope_kernel(const int* __restrict__ positions)
{
    const int total = T_TOKENS * 50 * 64;
    int idx = blockIdx.x * blockDim.x + threadIdx.x;
    if (idx >= total) return;
    int i = idx & 63;
    int n = (idx >> 6) % 50;
    int t = idx / (50 * 64);

    float inv = expf(-0.14391156831212787f * (float)i);
    float ang = (float)positions[t] * inv;
    float s, c;
    sincosf(ang, &s, &c);

    size_t base = (size_t)t * QKV_N + n * HD + i;
    float x1 = g_qkv[base];
    float x2 = g_qkv[base + 64];
    g_qkv[base]      = x1 * c - x2 * s;
    g_qkv[base + 64] = x2 * c + x1 * s;
}

// ===========================================================================
// Flash attention (fp32) — output stored tf32-rounded for the o-proj GEMM.
// ===========================================================================
__global__ __launch_bounds__(256) void attn_kernel()
{
    extern __shared__ float sm[];
    float* q_s = sm;                  // 64 x 132
    float* k_s = q_s + 64 * 132;      // 64 x 132
    float* v_s = k_s + 64 * 132;      // 64 x 128
    float* p_s = v_s + 64 * 128;      // 64 x 68

    const int qt   = blockIdx.x;
    const int head = blockIdx.y;
    const int b    = blockIdx.z;
    const int kvh  = head >> 2;
    const int tid  = threadIdx.x;
    const int ty   = tid >> 4;
    const int tx   = tid & 15;

    const size_t rowbase = (size_t)b * S_LEN * QKV_N;

    {
        const float* qb = g_qkv + rowbase + (size_t)(qt * 64) * QKV_N + head * HD;
#pragma unroll
        for (int i = tid; i < 2048; i += 256) {
            int r = i >> 5, c = (i & 31) << 2;
            *(float4*)(q_s + r * 132 + c) = *(const float4*)(qb + (size_t)r * QKV_N + c);
        }
    }

    float m[4], l[4], o[4][8];
#pragma unroll
    for (int i = 0; i < 4; i++) {
        m[i] = -1e30f; l[i] = 0.0f;
#pragma unroll
        for (int c = 0; c < 8; c++) o[i][c] = 0.0f;
    }
    const float scale = 0.08838834764831843f;

    for (int kt = 0; kt <= qt; kt++) {
        __syncthreads();
        const float* kb = g_qkv + rowbase + (size_t)(kt * 64) * QKV_N + (NQ + kvh) * HD;
        const float* vb = g_qkv + rowbase + (size_t)(kt * 64) * QKV_N + (NQ + NKV + kvh) * HD;
#pragma unroll
        for (int i = tid; i < 2048; i += 256) {
            int r = i >> 5, c = (i & 31) << 2;
            *(float4*)(k_s + r * 132 + c) = *(const float4*)(kb + (size_t)r * QKV_N + c);
            *(float4*)(v_s + r * 128 + c) = *(const float4*)(vb + (size_t)r * QKV_N + c);
        }
        __syncthreads();

        float s[4][4];
#pragma unroll
        for (int i = 0; i < 4; i++)
#pragma unroll
            for (int j = 0; j < 4; j++) s[i][j] = 0.0f;

#pragma unroll 8
        for (int d = 0; d < 128; d += 4) {
            float4 qa[4], ka[4];
#pragma unroll
            for (int i = 0; i < 4; i++)
                qa[i] = *(const float4*)(q_s + (ty * 4 + i) * 132 + d);
#pragma unroll
            for (int j = 0; j < 4; j++)
                ka[j] = *(const float4*)(k_s + (tx + 16 * j) * 132 + d);
#pragma unroll
            for (int i = 0; i < 4; i++)
#pragma unroll
                for (int j = 0; j < 4; j++)
                    s[i][j] += qa[i].x * ka[j].x + qa[i].y * ka[j].y +
                               qa[i].z * ka[j].z + qa[i].w * ka[j].w;
        }

#pragma unroll
        for (int i = 0; i < 4; i++) {
            int grow = qt * 64 + ty * 4 + i;
            float mx = -1e30f;
#pragma unroll
            for (int j = 0; j < 4; j++) {
                int gcol = kt * 64 + tx + 16 * j;
                float val = (gcol <= grow) ? s[i][j] * scale : -1e30f;
                s[i][j] = val;
                mx = fmaxf(mx, val);
            }
#pragma unroll
            for (int off = 8; off >= 1; off >>= 1)
                mx = fmaxf(mx, __shfl_xor_sync(0xffffffffu, mx, off));
            float mnew  = fmaxf(m[i], mx);
            float alpha = __expf(m[i] - mnew);
            float rsum = 0.0f;
#pragma unroll
            for (int j = 0; j < 4; j++) {
                float p = __expf(s[i][j] - mnew);
                p_s[(ty * 4 + i) * 68 + tx + 16 * j] = p;
                rsum += p;
            }
#pragma unroll
            for (int off = 8; off >= 1; off >>= 1)
                rsum += __shfl_xor_sync(0xffffffffu, rsum, off);
            l[i] = l[i] * alpha + rsum;
            m[i] = mnew;
#pragma unroll
            for (int c = 0; c < 8; c++) o[i][c] *= alpha;
        }
        __syncthreads();

#pragma unroll 8
        for (int kk = 0; kk < 64; kk++) {
            float4 vb0 = *(const float4*)(v_s + kk * 128 + tx * 8);
            float4 vb1 = *(const float4*)(v_s + kk * 128 + tx * 8 + 4);
#pragma unroll
            for (int i = 0; i < 4; i++) {
                float p = p_s[(ty * 4 + i) * 68 + kk];
                o[i][0] += p * vb0.x; o[i][1] += p * vb0.y;
                o[i][2] += p * vb0.z; o[i][3] += p * vb0.w;
                o[i][4] += p * vb1.x; o[i][5] += p * vb1.y;
                o[i][6] += p * vb1.z; o[i][7] += p * vb1.w;
            }
        }
    }

#pragma unroll
    for (int i = 0; i < 4; i++) {
        float inv = 1.0f / l[i];
        int t = b * S_LEN + qt * 64 + ty * 4 + i;
        float* ob = g_obuf + (size_t)t * HIDDEN + head * HD + tx * 8;
        float4 r0 = make_float4(
            __uint_as_float(tf32r(o[i][0] * inv)),
            __uint_as_float(tf32r(o[i][1] * inv)),
            __uint_as_float(tf32r(o[i][2] * inv)),
            __uint_as_float(tf32r(o[i][3] * inv)));
        float4 r1 = make_float4(
            __uint_as_float(tf32r(o[i][4] * inv)),
            __uint_as_float(tf32r(o[i][5] * inv)),
            __uint_as_float(tf32r(o[i][6] * inv)),
            __uint_as_float(tf32r(o[i][7] * inv)));
        *(float4*)(ob)     = r0;
        *(float4*)(ob + 4) = r1;
    }
}

// ===========================================================================
extern "C" void kernel_launch(void* const* d_in, const int* in_sizes, int n_in,
                              void* d_out, int out_size)
{
    const float* x         = (const float*)d_in[0];  // [T, 5120]
    const float* w_qkv     = (const float*)d_in[1];  // [5120, 7680]
    const float* w_o       = (const float*)d_in[2];  // [5120, 5120]
    const int*   positions = (const int*)d_in[3];    // [T]
    float*       out       = (float*)d_out;          // [T, 5120]

    float *qkv, *obuf, *xr, *wa, *wb;
    cudaGetSymbolAddress((void**)&qkv,  g_qkv);
    cudaGetSymbolAddress((void**)&obuf, g_obuf);
    cudaGetSymbolAddress((void**)&xr,   g_xr);
    cudaGetSymbolAddress((void**)&wa,   g_wa);
    cudaGetSymbolAddress((void**)&wb,   g_wb);

    cudaFuncSetAttribute(tc_gemm, cudaFuncAttributeMaxDynamicSharedMemorySize,
                         GEMM_SMEM);

    // 0) tf32-RNA pre-rounding: x copy; weights transposed to [N][K]
    {
        int n4x = (T_TOKENS * HIDDEN) / 4;
        cvt_tf32_kernel<<<(n4x + 255) / 256, 256>>>((const float4*)x, (float4*)xr, n4x);
        dim3 blk(32, 8);
        transpose_tf32_kernel<<<dim3(QKV_N / 32, HIDDEN / 32), blk>>>(w_qkv, wa, HIDDEN, QKV_N);
        transpose_tf32_kernel<<<dim3(HIDDEN / 32, HIDDEN / 32), blk>>>(w_o, wb, HIDDEN, HIDDEN);
    }

    // 1) QKV projection (tf32 mma.sync, 128x256 tile)
    {
        dim3 grid(QKV_N / 256, T_TOKENS / 128);
        tc_gemm<<<grid, 256, GEMM_SMEM>>>(xr, wa, qkv, T_TOKENS, QKV_N, KDIM);
    }

    // 2) RoPE
    {
        int total = T_TOKENS * 50 * 64;
        rope_kernel<<<(total + 255) / 256, 256>>>(positions);
    }

    // 3) Causal GQA flash attention (fp32)
    {
        size_t smem = (size_t)(64 * 132 * 2 + 64 * 128 + 64 * 68) * sizeof(float);
        cudaFuncSetAttribute(attn_kernel,
                             cudaFuncAttributeMaxDynamicSharedMemorySize, (int)smem);
        dim3 grid(16, NQ, 8);
        attn_kernel<<<grid, 256, smem>>>();
    }

    // 4) Output projection (tf32 mma.sync, 128x256 tile)
    {
        dim3 grid(HIDDEN / 256, T_TOKENS / 128);
        tc_gemm<<<grid, 256, GEMM_SMEM>>>(obuf, wb, out, T_TOKENS, HIDDEN, KDIM);
    }
}

// round 6
// speedup vs baseline: 1.3708x; 1.3708x over previous
#include <cuda_runtime.h>
#include <cstdint>
#include <math.h>

#define T_TOKENS 8192
#define HIDDEN   5120
#define NQ       40
#define NKV      10
#define HD       128
#define QKV_N    7680
#define S_LEN    1024
#define KDIM     5120

// Scratch (device globals: no allocation allowed anywhere)
__device__ float g_qkv[(size_t)T_TOKENS * QKV_N];
__device__ float g_obuf[(size_t)T_TOKENS * HIDDEN];
__device__ float g_xr [(size_t)T_TOKENS * HIDDEN];   // tf32-rounded x
__device__ float g_wa [(size_t)HIDDEN * QKV_N];      // tf32-rounded w_qkv^T [7680][5120]
__device__ float g_wb [(size_t)HIDDEN * HIDDEN];     // tf32-rounded w_o^T   [5120][5120]

// ===========================================================================
// helpers
// ===========================================================================
__device__ __forceinline__ uint32_t smem_u32(const void* p) {
    uint32_t a;
    asm("{ .reg .u64 t; cvta.to.shared.u64 t, %1; cvt.u32.u64 %0, t; }"
        : "=r"(a) : "l"(p));
    return a;
}

__device__ __forceinline__ uint32_t tf32r(float x) {
    uint32_t u;
    asm("cvt.rna.tf32.f32 %0, %1;" : "=r"(u) : "f"(x));
    return u;
}

__device__ __forceinline__ void cp_async16(uint32_t dst, const void* src) {
    asm volatile("cp.async.cg.shared.global [%0], [%1], 16;"
                 :: "r"(dst), "l"(src) : "memory");
}

__device__ __forceinline__ void ldsm_x4(uint32_t* r, uint32_t addr) {
    asm volatile("ldmatrix.sync.aligned.m8n8.x4.shared.b16 {%0,%1,%2,%3}, [%4];"
                 : "=r"(r[0]), "=r"(r[1]), "=r"(r[2]), "=r"(r[3]) : "r"(addr));
}

__device__ __forceinline__ void mma_tf32(float* d, const uint32_t* a,
                                         uint32_t b0, uint32_t b1) {
    asm volatile(
        "mma.sync.aligned.m16n8k8.row.col.f32.tf32.tf32.f32 "
        "{%0,%1,%2,%3}, {%4,%5,%6,%7}, {%8,%9}, {%0,%1,%2,%3};"
        : "+f"(d[0]), "+f"(d[1]), "+f"(d[2]), "+f"(d[3])
        : "r"(a[0]), "r"(a[1]), "r"(a[2]), "r"(a[3]), "r"(b0), "r"(b1));
}

// ===========================================================================
// tf32 rounded copy — for x
// ===========================================================================
__global__ void cvt_tf32_kernel(const float4* __restrict__ src,
                                float4* __restrict__ dst, int n4)
{
    int i = blockIdx.x * blockDim.x + threadIdx.x;
    if (i >= n4) return;
    float4 v = src[i];
    float4 o;
    o.x = __uint_as_float(tf32r(v.x));
    o.y = __uint_as_float(tf32r(v.y));
    o.z = __uint_as_float(tf32r(v.z));
    o.w = __uint_as_float(tf32r(v.w));
    dst[i] = o;
}

// ===========================================================================
// tf32 rounded transpose: src [R][C] -> dst [C][R]. R,C % 32 == 0.
// ===========================================================================
__global__ void transpose_tf32_kernel(const float* __restrict__ src,
                                      float* __restrict__ dst, int R, int C)
{
    __shared__ float tile[32][33];
    int bc = blockIdx.x * 32, br = blockIdx.y * 32;
    int tx = threadIdx.x, ty = threadIdx.y;
#pragma unroll
    for (int i = 0; i < 32; i += 8) {
        float v = src[(size_t)(br + ty + i) * C + bc + tx];
        tile[ty + i][tx] = __uint_as_float(tf32r(v));
    }
    __syncthreads();
#pragma unroll
    for (int i = 0; i < 32; i += 8)
        dst[(size_t)(bc + ty + i) * R + br + tx] = tile[tx][ty + i];
}

// ===========================================================================
// TF32 mma.sync GEMM (round-4 config, proven): C[M,N] = A[M,K] @ Bt[N,K]^T.
// Block 128x128, BK=32, 8 warps (2 x 4), warp tile 64x32, 2 CTAs/SM.
// ===========================================================================
#define A_ST_B 18432             // 128 rows * 144 B
#define B_ST_B 18432
#define STAGE_B (A_ST_B + B_ST_B)
#define GEMM_SMEM (2 * STAGE_B)  // 73728

__global__ __launch_bounds__(256, 2)
void tc_gemm(const float* __restrict__ A, const float* __restrict__ Bt,
             float* __restrict__ C, int M, int N, int K)
{
    extern __shared__ __align__(16) char smem[];
    const uint32_t sbase = smem_u32(smem);
    const int tid  = threadIdx.x;
    const int lane = tid & 31;
    const int wid  = tid >> 5;
    const int wm   = wid & 1;
    const int wn   = wid >> 1;
    const int bm = blockIdx.y * 128, bn = blockIdx.x * 128;

    const float* Ag = A  + (size_t)bm * K;
    const float* Bg = Bt + (size_t)bn * K;

    float acc[4][4][4];
#pragma unroll
    for (int i = 0; i < 4; i++)
#pragma unroll
        for (int j = 0; j < 4; j++)
#pragma unroll
            for (int q = 0; q < 4; q++) acc[i][j][q] = 0.0f;

#define ISSUE_CHUNK(c, st) do {                                              \
        uint32_t a_dst = sbase + (st) * STAGE_B;                             \
        uint32_t b_dst = a_dst + A_ST_B;                                     \
        _Pragma("unroll")                                                    \
        for (int i = 0; i < 4; i++) {                                        \
            int idx = i * 256 + tid;                                         \
            int row = idx >> 3, kq = idx & 7;                                \
            cp_async16(a_dst + row * 144 + kq * 16,                          \
                       Ag + (size_t)row * K + (c) * 32 + kq * 4);            \
            cp_async16(b_dst + row * 144 + kq * 16,                          \
                       Bg + (size_t)row * K + (c) * 32 + kq * 4);            \
        }                                                                    \
        asm volatile("cp.async.commit_group;" ::: "memory");                 \
    } while (0)

    ISSUE_CHUNK(0, 0);

    const uint32_t a_tbase = sbase
        + (uint32_t)((wm * 64 + ((lane >> 3) & 1) * 8 + (lane & 7)) * 144)
        + (uint32_t)((lane >> 4) * 16);
    const uint32_t b_tbase = sbase + A_ST_B
        + (uint32_t)((wn * 32 + (lane & 7) + ((lane >> 4) << 3)) * 144)
        + (uint32_t)(((lane >> 3) & 1) * 16);

    const int NCH = K / 32;
    for (int c = 0; c < NCH; c++) {
        const int st = c & 1;
        asm volatile("cp.async.wait_group 0;" ::: "memory");
        __syncthreads();
        if (c + 1 < NCH) ISSUE_CHUNK(c + 1, st ^ 1);

        const uint32_t a_base = a_tbase + st * STAGE_B;
        const uint32_t b_base = b_tbase + st * STAGE_B;

#pragma unroll
        for (int j = 0; j < 4; j++) {
            uint32_t afr[4][4];
#pragma unroll
            for (int mt = 0; mt < 4; mt++)
                ldsm_x4(afr[mt], a_base + mt * 2304 + j * 32);

            uint32_t bfr[2][4];
#pragma unroll
            for (int p = 0; p < 2; p++)
                ldsm_x4(bfr[p], b_base + p * 2304 + j * 32);

#pragma unroll
            for (int mt = 0; mt < 4; mt++)
#pragma unroll
                for (int nt = 0; nt < 4; nt++)
                    mma_tf32(acc[mt][nt], afr[mt],
                             bfr[nt >> 1][(nt & 1) * 2],
                             bfr[nt >> 1][(nt & 1) * 2 + 1]);
        }
    }

    const int erow = bm + wm * 64 + (lane >> 2);
    const int ecol = bn + wn * 32 + 2 * (lane & 3);
#pragma unroll
    for (int mt = 0; mt < 4; mt++) {
#pragma unroll
        for (int nt = 0; nt < 4; nt++) {
            float* p0 = C + (size_t)(erow + mt * 16) * N + ecol + nt * 8;
            float* p1 = p0 + 8 * N;
            *(float2*)p0 = make_float2(acc[mt][nt][0], acc[mt][nt][1]);
            *(float2*)p1 = make_float2(acc[mt][nt][2], acc[mt][nt][3]);
        }
    }
#undef ISSUE_CHUNK
}

// ===========================================================================
// RoPE in-place on q (heads 0..39) and k (heads 40..49) of g_qkv.
// ===========================================================================
__global__ void rope_kernel(const int* __restrict__ positions)
{
    const int total = T_TOKENS * 50 * 64;
    int idx = blockIdx.x * blockDim.x + threadIdx.x;
    if (idx >= total) return;
    int i = idx & 63;
    int n = (idx >> 6) % 50;
    int t = idx / (50 * 64);

    float inv = expf(-0.14391156831212787f * (float)i);
    float ang = (float)positions[t] * inv;
    float s, c;
    sincosf(ang, &s, &c);

    size_t base = (size_t)t * QKV_N + n * HD + i;
    float x1 = g_qkv[base];
    float x2 = g_qkv[base + 64];
    g_qkv[base]      = x1 * c - x2 * s;
    g_qkv[base + 64] = x2 * c + x1 * s;
}

// ===========================================================================
// Tensor-core flash attention (tf32 mma.sync).
// Grid (8 qtiles, 40 heads, 8 batch), 256 threads = 8 warps.
// CTA: 128 q-rows; kt tiles of 64. Warp w: q rows w*16..w*16+15, full 64 cols.
// Q,K staged K-major pitch 132 floats; V transposed [d][s] pitch 68;
// P bounced via per-warp smem region pitch 68.
// ===========================================================================
#define QS_OFF  0
#define KS_OFF  (128 * 132)               // floats
#define VS_OFF  (KS_OFF + 64 * 132)
#define PS_OFF  (VS_OFF + 128 * 68)
#define ATT_SMEM ((PS_OFF + 8 * 16 * 68) * 4)   // 171008 bytes

__global__ __launch_bounds__(256, 1) void attn_tc_kernel()
{
    extern __shared__ __align__(16) float sm[];
    const uint32_t sbase = smem_u32(sm);
    const int qt   = blockIdx.x;
    const int head = blockIdx.y;
    const int b    = blockIdx.z;
    const int kvh  = head >> 2;
    const int tid  = threadIdx.x;
    const int lane = tid & 31;
    const int w    = tid >> 5;

    const size_t rowbase = (size_t)b * S_LEN * QKV_N;

    // Load Q tile (128 x 128), tf32-rounded
    {
        const float* qb = g_qkv + rowbase + (size_t)(qt * 128) * QKV_N + head * HD;
#pragma unroll
        for (int i = tid; i < 4096; i += 256) {
            int r = i >> 5, c4 = i & 31;
            float4 v = *(const float4*)(qb + (size_t)r * QKV_N + c4 * 4);
            float4 o = make_float4(__uint_as_float(tf32r(v.x)), __uint_as_float(tf32r(v.y)),
                                   __uint_as_float(tf32r(v.z)), __uint_as_float(tf32r(v.w)));
            *(float4*)(sm + QS_OFF + r * 132 + c4 * 4) = o;
        }
    }

    // ldsm bases
    const uint32_t a_q = sbase + (uint32_t)(QS_OFF * 4)
        + (uint32_t)((w * 16 + (lane & 7) + ((lane >> 3) & 1) * 8) * 528)
        + (uint32_t)((lane >> 4) * 16);
    const uint32_t b_k = sbase + (uint32_t)(KS_OFF * 4)
        + (uint32_t)(((lane & 7) + ((lane >> 4) << 3)) * 528)
        + (uint32_t)(((lane >> 3) & 1) * 16);
    const uint32_t b_v = sbase + (uint32_t)(VS_OFF * 4)
        + (uint32_t)(((lane & 7) + ((lane >> 4) << 3)) * 272)
        + (uint32_t)(((lane >> 3) & 1) * 16);
    const uint32_t a_p = sbase + (uint32_t)(PS_OFF * 4) + (uint32_t)(w * 16 * 272)
        + (uint32_t)(((lane & 7) + ((lane >> 3) & 1) * 8) * 272)
        + (uint32_t)((lane >> 4) * 16);
    float* p_st = sm + PS_OFF + w * 16 * 68;

    float oacc[16][4];
#pragma unroll
    for (int i = 0; i < 16; i++)
#pragma unroll
        for (int q = 0; q < 4; q++) oacc[i][q] = 0.0f;
    float mrow0 = -1e30f, mrow1 = -1e30f, lrow0 = 0.0f, lrow1 = 0.0f;

    const float scale = 0.08838834764831843f;  // 1/sqrt(128)
    const int r0 = lane >> 2, q4 = lane & 3;
    const int grow0 = qt * 128 + w * 16 + r0;
    const int grow1 = grow0 + 8;
    const int d4 = tid >> 3, s0 = tid & 7;     // V-transpose mapping

    const int NKT = 2 * qt + 2;
    for (int kt = 0; kt < NKT; kt++) {
        __syncthreads();
        // Load K tile (64 x 128) tf32-rounded, K-major pitch 132
        const float* kb = g_qkv + rowbase + (size_t)(kt * 64) * QKV_N + (NQ + kvh) * HD;
#pragma unroll
        for (int i = tid; i < 2048; i += 256) {
            int r = i >> 5, c4 = i & 31;
            float4 v = *(const float4*)(kb + (size_t)r * QKV_N + c4 * 4);
            float4 o = make_float4(__uint_as_float(tf32r(v.x)), __uint_as_float(tf32r(v.y)),
                                   __uint_as_float(tf32r(v.z)), __uint_as_float(tf32r(v.w)));
            *(float4*)(sm + KS_OFF + r * 132 + c4 * 4) = o;
        }
        // Load V transposed: v_s[d][s], tf32-rounded
        const float* vb = g_qkv + rowbase + (size_t)(kt * 64) * QKV_N + (NQ + NKV + kvh) * HD;
#pragma unroll
        for (int st = 0; st < 8; st++) {
            int s = s0 + st * 8;
            float4 v = *(const float4*)(vb + (size_t)s * QKV_N + d4 * 4);
            sm[VS_OFF + (d4 * 4 + 0) * 68 + s] = __uint_as_float(tf32r(v.x));
            sm[VS_OFF + (d4 * 4 + 1) * 68 + s] = __uint_as_float(tf32r(v.y));
            sm[VS_OFF + (d4 * 4 + 2) * 68 + s] = __uint_as_float(tf32r(v.z));
            sm[VS_OFF + (d4 * 4 + 3) * 68 + s] = __uint_as_float(tf32r(v.w));
        }
        __syncthreads();

        // S = Q K^T (warp: 16 x 64)
        float sacc[8][4];
#pragma unroll
        for (int nt = 0; nt < 8; nt++)
#pragma unroll
            for (int q = 0; q < 4; q++) sacc[nt][q] = 0.0f;

#pragma unroll
        for (int j = 0; j < 16; j++) {
            uint32_t qf[4];
            ldsm_x4(qf, a_q + j * 32);
            uint32_t bf[4][4];
#pragma unroll
            for (int p = 0; p < 4; p++)
                ldsm_x4(bf[p], b_k + p * 8448 + j * 32);   // 8448 = 16*528
#pragma unroll
            for (int nt = 0; nt < 8; nt++)
                mma_tf32(sacc[nt], qf,
                         bf[nt >> 1][(nt & 1) * 2],
                         bf[nt >> 1][(nt & 1) * 2 + 1]);
        }

        // scale + causal mask
        const int cb = kt * 64 + 2 * q4;
#pragma unroll
        for (int nt = 0; nt < 8; nt++) {
            int c0 = cb + nt * 8, c1 = c0 + 1;
            sacc[nt][0] = (c0 <= grow0) ? sacc[nt][0] * scale : -1e30f;
            sacc[nt][1] = (c1 <= grow0) ? sacc[nt][1] * scale : -1e30f;
            sacc[nt][2] = (c0 <= grow1) ? sacc[nt][2] * scale : -1e30f;
            sacc[nt][3] = (c1 <= grow1) ? sacc[nt][3] * scale : -1e30f;
        }

        // row max
        float mx0 = -1e30f, mx1 = -1e30f;
#pragma unroll
        for (int nt = 0; nt < 8; nt++) {
            mx0 = fmaxf(mx0, fmaxf(sacc[nt][0], sacc[nt][1]));
            mx1 = fmaxf(mx1, fmaxf(sacc[nt][2], sacc[nt][3]));
        }
        mx0 = fmaxf(mx0, __shfl_xor_sync(0xffffffffu, mx0, 1));
        mx0 = fmaxf(mx0, __shfl_xor_sync(0xffffffffu, mx0, 2));
        mx1 = fmaxf(mx1, __shfl_xor_sync(0xffffffffu, mx1, 1));
        mx1 = fmaxf(mx1, __shfl_xor_sync(0xffffffffu, mx1, 2));

        float mnew0 = fmaxf(mrow0, mx0), mnew1 = fmaxf(mrow1, mx1);
        float alpha0 = __expf(mrow0 - mnew0), alpha1 = __expf(mrow1 - mnew1);

        // P = exp(S - m), write to per-warp smem (tf32-rounded), row sums
        float sum0 = 0.0f, sum1 = 0.0f;
#pragma unroll
        for (int nt = 0; nt < 8; nt++) {
            float p0 = __expf(sacc[nt][0] - mnew0);
            float p1 = __expf(sacc[nt][1] - mnew0);
            float p2 = __expf(sacc[nt][2] - mnew1);
            float p3 = __expf(sacc[nt][3] - mnew1);
            sum0 += p0 + p1; sum1 += p2 + p3;
            int coff = nt * 8 + 2 * q4;
            *(float2*)(p_st + r0 * 68 + coff) =
                make_float2(__uint_as_float(tf32r(p0)), __uint_as_float(tf32r(p1)));
            *(float2*)(p_st + (r0 + 8) * 68 + coff) =
                make_float2(__uint_as_float(tf32r(p2)), __uint_as_float(tf32r(p3)));
        }
        sum0 += __shfl_xor_sync(0xffffffffu, sum0, 1);
        sum0 += __shfl_xor_sync(0xffffffffu, sum0, 2);
        sum1 += __shfl_xor_sync(0xffffffffu, sum1, 1);
        sum1 += __shfl_xor_sync(0xffffffffu, sum1, 2);

        lrow0 = lrow0 * alpha0 + sum0;
        lrow1 = lrow1 * alpha1 + sum1;
        mrow0 = mnew0; mrow1 = mnew1;

#pragma unroll
        for (int nt = 0; nt < 16; nt++) {
            oacc[nt][0] *= alpha0; oacc[nt][1] *= alpha0;
            oacc[nt][2] *= alpha1; oacc[nt][3] *= alpha1;
        }
        __syncwarp();

        // O += P V  (A = P from smem, B = V^T)
#pragma unroll
        for (int jj = 0; jj < 8; jj++) {
            uint32_t pf[4];
            ldsm_x4(pf, a_p + jj * 32);
#pragma unroll
            for (int p8 = 0; p8 < 8; p8++) {
                uint32_t bf[4];
                ldsm_x4(bf, b_v + p8 * 4352 + jj * 32);   // 4352 = 16*272
                mma_tf32(oacc[p8 * 2],     pf, bf[0], bf[1]);
                mma_tf32(oacc[p8 * 2 + 1], pf, bf[2], bf[3]);
            }
        }
    }

    // Epilogue: normalize, tf32-round, write to g_obuf
    float inv0 = 1.0f / lrow0, inv1 = 1.0f / lrow1;
    int t0 = b * S_LEN + qt * 128 + w * 16 + r0;
    int t1 = t0 + 8;
#pragma unroll
    for (int nt = 0; nt < 16; nt++) {
        int col = head * HD + nt * 8 + 2 * q4;
        *(float2*)(g_obuf + (size_t)t0 * HIDDEN + col) =
            make_float2(__uint_as_float(tf32r(oacc[nt][0] * inv0)),
                        __uint_as_float(tf32r(oacc[nt][1] * inv0)));
        *(float2*)(g_obuf + (size_t)t1 * HIDDEN + col) =
            make_float2(__uint_as_float(tf32r(oacc[nt][2] * inv1)),
                        __uint_as_float(tf32r(oacc[nt][3] * inv1)));
    }
}

// ===========================================================================
extern "C" void kernel_launch(void* const* d_in, const int* in_sizes, int n_in,
                              void* d_out, int out_size)
{
    const float* x         = (const float*)d_in[0];  // [T, 5120]
    const float* w_qkv     = (const float*)d_in[1];  // [5120, 7680]
    const float* w_o       = (const float*)d_in[2];  // [5120, 5120]
    const int*   positions = (const int*)d_in[3];    // [T]
    float*       out       = (float*)d_out;          // [T, 5120]

    float *qkv, *obuf, *xr, *wa, *wb;
    cudaGetSymbolAddress((void**)&qkv,  g_qkv);
    cudaGetSymbolAddress((void**)&obuf, g_obuf);
    cudaGetSymbolAddress((void**)&xr,   g_xr);
    cudaGetSymbolAddress((void**)&wa,   g_wa);
    cudaGetSymbolAddress((void**)&wb,   g_wb);

    cudaFuncSetAttribute(tc_gemm, cudaFuncAttributeMaxDynamicSharedMemorySize,
                         GEMM_SMEM);
    cudaFuncSetAttribute(attn_tc_kernel, cudaFuncAttributeMaxDynamicSharedMemorySize,
                         ATT_SMEM);

    // 0) tf32-RNA pre-rounding: x copy; weights transposed to [N][K]
    {
        int n4x = (T_TOKENS * HIDDEN) / 4;
        cvt_tf32_kernel<<<(n4x + 255) / 256, 256>>>((const float4*)x, (float4*)xr, n4x);
        dim3 blk(32, 8);
        transpose_tf32_kernel<<<dim3(QKV_N / 32, HIDDEN / 32), blk>>>(w_qkv, wa, HIDDEN, QKV_N);
        transpose_tf32_kernel<<<dim3(HIDDEN / 32, HIDDEN / 32), blk>>>(w_o, wb, HIDDEN, HIDDEN);
    }

    // 1) QKV projection
    {
        dim3 grid(QKV_N / 128, T_TOKENS / 128);
        tc_gemm<<<grid, 256, GEMM_SMEM>>>(xr, wa, qkv, T_TOKENS, QKV_N, KDIM);
    }

    // 2) RoPE
    {
        int total = T_TOKENS * 50 * 64;
        rope_kernel<<<(total + 255) / 256, 256>>>(positions);
    }

    // 3) Causal GQA flash attention (tf32 tensor cores)
    {
        dim3 grid(8, NQ, 8);
        attn_tc_kernel<<<grid, 256, ATT_SMEM>>>();
    }

    // 4) Output projection
    {
        dim3 grid(HIDDEN / 128, T_TOKENS / 128);
        tc_gemm<<<grid, 256, GEMM_SMEM>>>(obuf, wb, out, T_TOKENS, HIDDEN, KDIM);
    }
}

// round 7
// speedup vs baseline: 2.1667x; 1.5806x over previous
#include <cuda_runtime.h>
#include <cuda_fp16.h>
#include <cstdint>
#include <math.h>

#define T_TOKENS 8192
#define HIDDEN   5120
#define NQ       40
#define NKV      10
#define HD       128
#define QKV_N    7680
#define S_LEN    1024
#define KDIM     5120

// Scratch (device globals: no allocation allowed anywhere)
__device__ float  g_qkv[(size_t)T_TOKENS * QKV_N];   // fp32 qkv (rope + attn input)
__device__ __half g_oh [(size_t)T_TOKENS * HIDDEN];  // fp16 attention output
__device__ __half g_xh [(size_t)T_TOKENS * HIDDEN];  // fp16 x
__device__ __half g_wah[(size_t)HIDDEN * QKV_N];     // fp16 w_qkv^T [7680][5120]
__device__ __half g_wbh[(size_t)HIDDEN * HIDDEN];    // fp16 w_o^T   [5120][5120]

// ===========================================================================
// helpers
// ===========================================================================
__device__ __forceinline__ uint32_t smem_u32(const void* p) {
    uint32_t a;
    asm("{ .reg .u64 t; cvta.to.shared.u64 t, %1; cvt.u32.u64 %0, t; }"
        : "=r"(a) : "l"(p));
    return a;
}

__device__ __forceinline__ uint32_t tf32r(float x) {
    uint32_t u;
    asm("cvt.rna.tf32.f32 %0, %1;" : "=r"(u) : "f"(x));
    return u;
}

__device__ __forceinline__ void cp_async16(uint32_t dst, const void* src) {
    asm volatile("cp.async.cg.shared.global [%0], [%1], 16;"
                 :: "r"(dst), "l"(src) : "memory");
}

__device__ __forceinline__ void ldsm_x4(uint32_t* r, uint32_t addr) {
    asm volatile("ldmatrix.sync.aligned.m8n8.x4.shared.b16 {%0,%1,%2,%3}, [%4];"
                 : "=r"(r[0]), "=r"(r[1]), "=r"(r[2]), "=r"(r[3]) : "r"(addr));
}

// tf32 m16n8k8 (attention)
__device__ __forceinline__ void mma_tf32(float* d, const uint32_t* a,
                                         uint32_t b0, uint32_t b1) {
    asm volatile(
        "mma.sync.aligned.m16n8k8.row.col.f32.tf32.tf32.f32 "
        "{%0,%1,%2,%3}, {%4,%5,%6,%7}, {%8,%9}, {%0,%1,%2,%3};"
        : "+f"(d[0]), "+f"(d[1]), "+f"(d[2]), "+f"(d[3])
        : "r"(a[0]), "r"(a[1]), "r"(a[2]), "r"(a[3]), "r"(b0), "r"(b1));
}

// fp16 m16n8k16, fp32 accumulate (GEMMs)
__device__ __forceinline__ void mma_f16(float* d, const uint32_t* a,
                                        uint32_t b0, uint32_t b1) {
    asm volatile(
        "mma.sync.aligned.m16n8k16.row.col.f32.f16.f16.f32 "
        "{%0,%1,%2,%3}, {%4,%5,%6,%7}, {%8,%9}, {%0,%1,%2,%3};"
        : "+f"(d[0]), "+f"(d[1]), "+f"(d[2]), "+f"(d[3])
        : "r"(a[0]), "r"(a[1]), "r"(a[2]), "r"(a[3]), "r"(b0), "r"(b1));
}

// ===========================================================================
// fp32 -> fp16 copy (for x). 8 elements / thread.
// ===========================================================================
__global__ void cvt_f16_kernel(const float4* __restrict__ src,
                               uint4* __restrict__ dst, int n8)
{
    int i = blockIdx.x * blockDim.x + threadIdx.x;
    if (i >= n8) return;
    float4 v0 = src[2 * i], v1 = src[2 * i + 1];
    __half2 h0 = __floats2half2_rn(v0.x, v0.y);
    __half2 h1 = __floats2half2_rn(v0.z, v0.w);
    __half2 h2 = __floats2half2_rn(v1.x, v1.y);
    __half2 h3 = __floats2half2_rn(v1.z, v1.w);
    uint4 o;
    o.x = *(uint32_t*)&h0; o.y = *(uint32_t*)&h1;
    o.z = *(uint32_t*)&h2; o.w = *(uint32_t*)&h3;
    dst[i] = o;
}

// ===========================================================================
// fp32 -> fp16 transpose: src [R][C] f32 -> dst [C][R] f16. R,C % 32 == 0.
// ===========================================================================
__global__ void transpose_f16_kernel(const float* __restrict__ src,
                                     __half* __restrict__ dst, int R, int C)
{
    __shared__ float tile[32][33];
    int bc = blockIdx.x * 32, br = blockIdx.y * 32;
    int tx = threadIdx.x, ty = threadIdx.y;
#pragma unroll
    for (int i = 0; i < 32; i += 8)
        tile[ty + i][tx] = src[(size_t)(br + ty + i) * C + bc + tx];
    __syncthreads();
#pragma unroll
    for (int i = 0; i < 32; i += 8)
        dst[(size_t)(bc + ty + i) * R + br + tx] = __float2half_rn(tile[tx][ty + i]);
}

// ===========================================================================
// FP16 mma.sync GEMM: C[M,N] = A[M,K] @ Bt[N,K]^T, fp32 accum/output.
// Block 128x128, BK=32 (64B rows, 80B pitch), 8 warps (2x4), warp tile
// 64x32, 3-stage cp.async pipeline, 2 CTAs/SM.
// ===========================================================================
#define HSTAGE_A 10240           // 128 rows * 80 B
#define HSTAGE_B (2 * HSTAGE_A)  // 20480
#define HGEMM_SMEM (3 * HSTAGE_B)  // 61440

__global__ __launch_bounds__(256, 2)
void hgemm(const __half* __restrict__ A, const __half* __restrict__ Bt,
           float* __restrict__ C, int M, int N, int K)
{
    extern __shared__ __align__(16) char smem[];
    const uint32_t sbase = smem_u32(smem);
    const int tid  = threadIdx.x;
    const int lane = tid & 31;
    const int wid  = tid >> 5;
    const int wm   = wid & 1;
    const int wn   = wid >> 1;
    const int bm = blockIdx.y * 128, bn = blockIdx.x * 128;

    const __half* Ag = A  + (size_t)bm * K;
    const __half* Bg = Bt + (size_t)bn * K;

    float acc[4][4][4];
#pragma unroll
    for (int i = 0; i < 4; i++)
#pragma unroll
        for (int j = 0; j < 4; j++)
#pragma unroll
            for (int q = 0; q < 4; q++) acc[i][j][q] = 0.0f;

#define ISSUE_CHUNK(c, st) do {                                              \
        uint32_t a_dst = sbase + (st) * HSTAGE_B;                            \
        uint32_t b_dst = a_dst + HSTAGE_A;                                   \
        _Pragma("unroll")                                                    \
        for (int i = 0; i < 2; i++) {                                        \
            int idx = i * 256 + tid;                                         \
            int row = idx >> 2, kq = idx & 3;                                \
            cp_async16(a_dst + row * 80 + kq * 16,                           \
                       Ag + (size_t)row * K + (c) * 32 + kq * 8);            \
            cp_async16(b_dst + row * 80 + kq * 16,                           \
                       Bg + (size_t)row * K + (c) * 32 + kq * 8);            \
        }                                                                    \
        asm volatile("cp.async.commit_group;" ::: "memory");                 \
    } while (0)

    ISSUE_CHUNK(0, 0);
    ISSUE_CHUNK(1, 1);

    // ldsm bases
    // A: lanes 0-15 -> rows 0-15 (k-chunk 0), lanes 16-31 -> same rows +16B
    const uint32_t a_tbase = sbase
        + (uint32_t)((wm * 64 + (lane & 15)) * 80)
        + (uint32_t)((lane >> 4) * 16);
    // B: lanes 0-7 n-rows 0-7 chunk0; 8-15 rows 0-7 chunk1;
    //    16-23 rows 8-15 chunk0; 24-31 rows 8-15 chunk1
    const uint32_t b_tbase = sbase + HSTAGE_A
        + (uint32_t)((wn * 32 + (lane & 7) + ((lane >> 4) << 3)) * 80)
        + (uint32_t)(((lane >> 3) & 1) * 16);

    const int NCH = K / 32;
    for (int c = 0; c < NCH; c++) {
        const int st = c % 3;
        asm volatile("cp.async.wait_group 1;" ::: "memory");
        __syncthreads();
        if (c + 2 < NCH) ISSUE_CHUNK(c + 2, (c + 2) % 3);

        const uint32_t a_base = a_tbase + st * HSTAGE_B;
        const uint32_t b_base = b_tbase + st * HSTAGE_B;

#pragma unroll
        for (int j = 0; j < 2; j++) {          // two k16 steps per 32-chunk
            uint32_t afr[4][4];
#pragma unroll
            for (int mt = 0; mt < 4; mt++)
                ldsm_x4(afr[mt], a_base + mt * 1280 + j * 32);  // 1280 = 16*80

            uint32_t bfr[2][4];
#pragma unroll
            for (int p = 0; p < 2; p++)
                ldsm_x4(bfr[p], b_base + p * 1280 + j * 32);

#pragma unroll
            for (int mt = 0; mt < 4; mt++)
#pragma unroll
                for (int nt = 0; nt < 4; nt++)
                    mma_f16(acc[mt][nt], afr[mt],
                            bfr[nt >> 1][(nt & 1) * 2],
                            bfr[nt >> 1][(nt & 1) * 2 + 1]);
        }
    }

    const int erow = bm + wm * 64 + (lane >> 2);
    const int ecol = bn + wn * 32 + 2 * (lane & 3);
#pragma unroll
    for (int mt = 0; mt < 4; mt++) {
#pragma unroll
        for (int nt = 0; nt < 4; nt++) {
            float* p0 = C + (size_t)(erow + mt * 16) * N + ecol + nt * 8;
            float* p1 = p0 + 8 * N;
            *(float2*)p0 = make_float2(acc[mt][nt][0], acc[mt][nt][1]);
            *(float2*)p1 = make_float2(acc[mt][nt][2], acc[mt][nt][3]);
        }
    }
#undef ISSUE_CHUNK
}

// ===========================================================================
// RoPE in-place on q (heads 0..39) and k (heads 40..49) of g_qkv.
// ===========================================================================
__global__ void rope_kernel(const int* __restrict__ positions)
{
    const int total = T_TOKENS * 50 * 64;
    int idx = blockIdx.x * blockDim.x + threadIdx.x;
    if (idx >= total) return;
    int i = idx & 63;
    int n = (idx >> 6) % 50;
    int t = idx / (50 * 64);

    float inv = expf(-0.14391156831212787f * (float)i);
    float ang = (float)positions[t] * inv;
    float s, c;
    sincosf(ang, &s, &c);

    size_t base = (size_t)t * QKV_N + n * HD + i;
    float x1 = g_qkv[base];
    float x2 = g_qkv[base + 64];
    g_qkv[base]      = x1 * c - x2 * s;
    g_qkv[base + 64] = x2 * c + x1 * s;
}

// ===========================================================================
// Tensor-core flash attention (tf32 mma.sync) — unchanged from round 6
// except the epilogue writes fp16 to g_oh.
// ===========================================================================
#define QS_OFF  0
#define KS_OFF  (128 * 132)
#define VS_OFF  (KS_OFF + 64 * 132)
#define PS_OFF  (VS_OFF + 128 * 68)
#define ATT_SMEM ((PS_OFF + 8 * 16 * 68) * 4)

__global__ __launch_bounds__(256, 1) void attn_tc_kernel()
{
    extern __shared__ __align__(16) float sm[];
    const uint32_t sbase = smem_u32(sm);
    const int qt   = blockIdx.x;
    const int head = blockIdx.y;
    const int b    = blockIdx.z;
    const int kvh  = head >> 2;
    const int tid  = threadIdx.x;
    const int lane = tid & 31;
    const int w    = tid >> 5;

    const size_t rowbase = (size_t)b * S_LEN * QKV_N;

    {
        const float* qb = g_qkv + rowbase + (size_t)(qt * 128) * QKV_N + head * HD;
#pragma unroll
        for (int i = tid; i < 4096; i += 256) {
            int r = i >> 5, c4 = i & 31;
            float4 v = *(const float4*)(qb + (size_t)r * QKV_N + c4 * 4);
            float4 o = make_float4(__uint_as_float(tf32r(v.x)), __uint_as_float(tf32r(v.y)),
                                   __uint_as_float(tf32r(v.z)), __uint_as_float(tf32r(v.w)));
            *(float4*)(sm + QS_OFF + r * 132 + c4 * 4) = o;
        }
    }

    const uint32_t a_q = sbase + (uint32_t)(QS_OFF * 4)
        + (uint32_t)((w * 16 + (lane & 7) + ((lane >> 3) & 1) * 8) * 528)
        + (uint32_t)((lane >> 4) * 16);
    const uint32_t b_k = sbase + (uint32_t)(KS_OFF * 4)
        + (uint32_t)(((lane & 7) + ((lane >> 4) << 3)) * 528)
        + (uint32_t)(((lane >> 3) & 1) * 16);
    const uint32_t b_v = sbase + (uint32_t)(VS_OFF * 4)
        + (uint32_t)(((lane & 7) + ((lane >> 4) << 3)) * 272)
        + (uint32_t)(((lane >> 3) & 1) * 16);
    const uint32_t a_p = sbase + (uint32_t)(PS_OFF * 4) + (uint32_t)(w * 16 * 272)
        + (uint32_t)(((lane & 7) + ((lane >> 3) & 1) * 8) * 272)
        + (uint32_t)((lane >> 4) * 16);
    float* p_st = sm + PS_OFF + w * 16 * 68;

    float oacc[16][4];
#pragma unroll
    for (int i = 0; i < 16; i++)
#pragma unroll
        for (int q = 0; q < 4; q++) oacc[i][q] = 0.0f;
    float mrow0 = -1e30f, mrow1 = -1e30f, lrow0 = 0.0f, lrow1 = 0.0f;

    const float scale = 0.08838834764831843f;
    const int r0 = lane >> 2, q4 = lane & 3;
    const int grow0 = qt * 128 + w * 16 + r0;
    const int grow1 = grow0 + 8;
    const int d4 = tid >> 3, s0 = tid & 7;

    const int NKT = 2 * qt + 2;
    for (int kt = 0; kt < NKT; kt++) {
        __syncthreads();
        const float* kb = g_qkv + rowbase + (size_t)(kt * 64) * QKV_N + (NQ + kvh) * HD;
#pragma unroll
        for (int i = tid; i < 2048; i += 256) {
            int r = i >> 5, c4 = i & 31;
            float4 v = *(const float4*)(kb + (size_t)r * QKV_N + c4 * 4);
            float4 o = make_float4(__uint_as_float(tf32r(v.x)), __uint_as_float(tf32r(v.y)),
                                   __uint_as_float(tf32r(v.z)), __uint_as_float(tf32r(v.w)));
            *(float4*)(sm + KS_OFF + r * 132 + c4 * 4) = o;
        }
        const float* vb = g_qkv + rowbase + (size_t)(kt * 64) * QKV_N + (NQ + NKV + kvh) * HD;
#pragma unroll
        for (int st = 0; st < 8; st++) {
            int s = s0 + st * 8;
            float4 v = *(const float4*)(vb + (size_t)s * QKV_N + d4 * 4);
            sm[VS_OFF + (d4 * 4 + 0) * 68 + s] = __uint_as_float(tf32r(v.x));
            sm[VS_OFF + (d4 * 4 + 1) * 68 + s] = __uint_as_float(tf32r(v.y));
            sm[VS_OFF + (d4 * 4 + 2) * 68 + s] = __uint_as_float(tf32r(v.z));
            sm[VS_OFF + (d4 * 4 + 3) * 68 + s] = __uint_as_float(tf32r(v.w));
        }
        __syncthreads();

        float sacc[8][4];
#pragma unroll
        for (int nt = 0; nt < 8; nt++)
#pragma unroll
            for (int q = 0; q < 4; q++) sacc[nt][q] = 0.0f;

#pragma unroll
        for (int j = 0; j < 16; j++) {
            uint32_t qf[4];
            ldsm_x4(qf, a_q + j * 32);
            uint32_t bf[4][4];
#pragma unroll
            for (int p = 0; p < 4; p++)
                ldsm_x4(bf[p], b_k + p * 8448 + j * 32);
#pragma unroll
            for (int nt = 0; nt < 8; nt++)
                mma_tf32(sacc[nt], qf,
                         bf[nt >> 1][(nt & 1) * 2],
                         bf[nt >> 1][(nt & 1) * 2 + 1]);
        }

        const int cb = kt * 64 + 2 * q4;
#pragma unroll
        for (int nt = 0; nt < 8; nt++) {
            int c0 = cb + nt * 8, c1 = c0 + 1;
            sacc[nt][0] = (c0 <= grow0) ? sacc[nt][0] * scale : -1e30f;
            sacc[nt][1] = (c1 <= grow0) ? sacc[nt][1] * scale : -1e30f;
            sacc[nt][2] = (c0 <= grow1) ? sacc[nt][2] * scale : -1e30f;
            sacc[nt][3] = (c1 <= grow1) ? sacc[nt][3] * scale : -1e30f;
        }

        float mx0 = -1e30f, mx1 = -1e30f;
#pragma unroll
        for (int nt = 0; nt < 8; nt++) {
            mx0 = fmaxf(mx0, fmaxf(sacc[nt][0], sacc[nt][1]));
            mx1 = fmaxf(mx1, fmaxf(sacc[nt][2], sacc[nt][3]));
        }
        mx0 = fmaxf(mx0, __shfl_xor_sync(0xffffffffu, mx0, 1));
        mx0 = fmaxf(mx0, __shfl_xor_sync(0xffffffffu, mx0, 2));
        mx1 = fmaxf(mx1, __shfl_xor_sync(0xffffffffu, mx1, 1));
        mx1 = fmaxf(mx1, __shfl_xor_sync(0xffffffffu, mx1, 2));

        float mnew0 = fmaxf(mrow0, mx0), mnew1 = fmaxf(mrow1, mx1);
        float alpha0 = __expf(mrow0 - mnew0), alpha1 = __expf(mrow1 - mnew1);

        float sum0 = 0.0f, sum1 = 0.0f;
#pragma unroll
        for (int nt = 0; nt < 8; nt++) {
            float p0 = __expf(sacc[nt][0] - mnew0);
            float p1 = __expf(sacc[nt][1] - mnew0);
            float p2 = __expf(sacc[nt][2] - mnew1);
            float p3 = __expf(sacc[nt][3] - mnew1);
            sum0 += p0 + p1; sum1 += p2 + p3;
            int coff = nt * 8 + 2 * q4;
            *(float2*)(p_st + r0 * 68 + coff) =
                make_float2(__uint_as_float(tf32r(p0)), __uint_as_float(tf32r(p1)));
            *(float2*)(p_st + (r0 + 8) * 68 + coff) =
                make_float2(__uint_as_float(tf32r(p2)), __uint_as_float(tf32r(p3)));
        }
        sum0 += __shfl_xor_sync(0xffffffffu, sum0, 1);
        sum0 += __shfl_xor_sync(0xffffffffu, sum0, 2);
        sum1 += __shfl_xor_sync(0xffffffffu, sum1, 1);
        sum1 += __shfl_xor_sync(0xffffffffu, sum1, 2);

        lrow0 = lrow0 * alpha0 + sum0;
        lrow1 = lrow1 * alpha1 + sum1;
        mrow0 = mnew0; mrow1 = mnew1;

#pragma unroll
        for (int nt = 0; nt < 16; nt++) {
            oacc[nt][0] *= alpha0; oacc[nt][1] *= alpha0;
            oacc[nt][2] *= alpha1; oacc[nt][3] *= alpha1;
        }
        __syncwarp();

#pragma unroll
        for (int jj = 0; jj < 8; jj++) {
            uint32_t pf[4];
            ldsm_x4(pf, a_p + jj * 32);
#pragma unroll
            for (int p8 = 0; p8 < 8; p8++) {
                uint32_t bf[4];
                ldsm_x4(bf, b_v + p8 * 4352 + jj * 32);
                mma_tf32(oacc[p8 * 2],     pf, bf[0], bf[1]);
                mma_tf32(oacc[p8 * 2 + 1], pf, bf[2], bf[3]);
            }
        }
    }

    // Epilogue: normalize, write fp16 to g_oh
    float inv0 = 1.0f / lrow0, inv1 = 1.0f / lrow1;
    int t0 = b * S_LEN + qt * 128 + w * 16 + r0;
    int t1 = t0 + 8;
#pragma unroll
    for (int nt = 0; nt < 16; nt++) {
        int col = head * HD + nt * 8 + 2 * q4;
        __half2 h0 = __floats2half2_rn(oacc[nt][0] * inv0, oacc[nt][1] * inv0);
        __half2 h1 = __floats2half2_rn(oacc[nt][2] * inv1, oacc[nt][3] * inv1);
        *(__half2*)(g_oh + (size_t)t0 * HIDDEN + col) = h0;
        *(__half2*)(g_oh + (size_t)t1 * HIDDEN + col) = h1;
    }
}

// ===========================================================================
extern "C" void kernel_launch(void* const* d_in, const int* in_sizes, int n_in,
                              void* d_out, int out_size)
{
    const float* x         = (const float*)d_in[0];  // [T, 5120]
    const float* w_qkv     = (const float*)d_in[1];  // [5120, 7680]
    const float* w_o       = (const float*)d_in[2];  // [5120, 5120]
    const int*   positions = (const int*)d_in[3];    // [T]
    float*       out       = (float*)d_out;          // [T, 5120]

    float* qkv = nullptr;
    __half *oh, *xh, *wah, *wbh;
    cudaGetSymbolAddress((void**)&qkv, g_qkv);
    cudaGetSymbolAddress((void**)&oh,  g_oh);
    cudaGetSymbolAddress((void**)&xh,  g_xh);
    cudaGetSymbolAddress((void**)&wah, g_wah);
    cudaGetSymbolAddress((void**)&wbh, g_wbh);

    cudaFuncSetAttribute(hgemm, cudaFuncAttributeMaxDynamicSharedMemorySize,
                         HGEMM_SMEM);
    cudaFuncSetAttribute(attn_tc_kernel, cudaFuncAttributeMaxDynamicSharedMemorySize,
                         ATT_SMEM);

    // 0) fp16 pre-pass: x copy; weights transposed to [N][K]
    {
        int n8x = (T_TOKENS * HIDDEN) / 8;
        cvt_f16_kernel<<<(n8x + 255) / 256, 256>>>((const float4*)x, (uint4*)xh, n8x);
        dim3 blk(32, 8);
        transpose_f16_kernel<<<dim3(QKV_N / 32, HIDDEN / 32), blk>>>(w_qkv, wah, HIDDEN, QKV_N);
        transpose_f16_kernel<<<dim3(HIDDEN / 32, HIDDEN / 32), blk>>>(w_o, wbh, HIDDEN, HIDDEN);
    }

    // 1) QKV projection (fp16 mma, fp32 accum)
    {
        dim3 grid(QKV_N / 128, T_TOKENS / 128);
        hgemm<<<grid, 256, HGEMM_SMEM>>>(xh, wah, qkv, T_TOKENS, QKV_N, KDIM);
    }

    // 2) RoPE
    {
        int total = T_TOKENS * 50 * 64;
        rope_kernel<<<(total + 255) / 256, 256>>>(positions);
    }

    // 3) Causal GQA flash attention (tf32 tensor cores)
    {
        dim3 grid(8, NQ, 8);
        attn_tc_kernel<<<grid, 256, ATT_SMEM>>>();
    }

    // 4) Output projection (fp16 mma, fp32 accum)
    {
        dim3 grid(HIDDEN / 128, T_TOKENS / 128);
        hgemm<<<grid, 256, HGEMM_SMEM>>>(oh, wbh, out, T_TOKENS, HIDDEN, KDIM);
    }
}